// round 8
// baseline (speedup 1.0000x reference)
#include <cuda_runtime.h>
#include <cstdint>
#include <cstddef>

// Problem constants
#define B_WIN  200
#define S_DIM  14
#define HW     196           // 14*14
#define C_DIM  768
#define NH     12
#define HD     64
#define M_TOK  (B_WIN * HW)  // 39200
#define QKV_N  (3 * C_DIM)   // 2304
#define NHEADS_TOT (B_WIN * NH)   // 2400

// Scratch (device globals: allocation-free per harness rules)
__device__ float g_qkv[(size_t)M_TOK * QKV_N];          // (B*HW, 2304)
__device__ float g_ctx[(size_t)M_TOK * C_DIM];          // (B*HW, 768) tf32-rounded
__device__ float g_at[(size_t)NHEADS_TOT * HW * 200];   // probs (tf32), row stride 200
__device__ float g_xc[(size_t)M_TOK * C_DIM];           // x, tf32-rounded
__device__ float g_wqkv[(size_t)C_DIM * QKV_N];         // w_qkv, tf32-rounded
__device__ float g_wproj[(size_t)C_DIM * C_DIM];        // w_proj, tf32-rounded

// ---------------------------------------------------------------------------
// tf32 helpers
// ---------------------------------------------------------------------------
__device__ __forceinline__ float f2tf32(float x) {
    uint32_t r;
    asm("cvt.rna.tf32.f32 %0, %1;" : "=r"(r) : "f"(x));
    return __uint_as_float(r);
}

__device__ __forceinline__ void mma_tf32(float* c, const uint32_t* a, const uint32_t* b) {
    asm volatile(
        "mma.sync.aligned.m16n8k8.row.col.f32.tf32.tf32.f32 "
        "{%0,%1,%2,%3}, {%4,%5,%6,%7}, {%8,%9}, {%0,%1,%2,%3};"
        : "+f"(c[0]), "+f"(c[1]), "+f"(c[2]), "+f"(c[3])
        : "r"(a[0]), "r"(a[1]), "r"(a[2]), "r"(a[3]),
          "r"(b[0]), "r"(b[1]));
}

// ---------------------------------------------------------------------------
// Pre-pass: tf32-round a buffer (float4 grid-stride).
// ---------------------------------------------------------------------------
__global__ void cvt_tf32_kernel(const float* __restrict__ src,
                                float* __restrict__ dst, int n4) {
    int i = blockIdx.x * blockDim.x + threadIdx.x;
    int stride = gridDim.x * blockDim.x;
    for (; i < n4; i += stride) {
        float4 v = *(const float4*)(src + (size_t)i * 4);
        v.x = f2tf32(v.x); v.y = f2tf32(v.y); v.z = f2tf32(v.z); v.w = f2tf32(v.w);
        *(float4*)(dst + (size_t)i * 4) = v;
    }
}

// ---------------------------------------------------------------------------
// Tensor-core tf32 GEMM, cp.async double-buffered, 3 CTAs/SM.
// C = A(MxK) @ B(KxN) + bias(N). BM=128, BN=64, BK=32.
// 256 threads = 8 warps in 4(m) x 2(n); warp tile 32x32 (2 m-tiles x 4 n-tiles).
// Inputs pre-rounded to tf32 in GMEM -> fragments are plain LDS.
// ---------------------------------------------------------------------------
#define BM 128
#define BN 64
#define BK 32

#define GA_STR 36
#define GB_STR 72
#define GA_SZ  (BM * GA_STR)          // 4608 floats / stage
#define GB_SZ  (BK * GB_STR)          // 2304 floats / stage
#define G_SMEM_FLOATS (2 * GA_SZ + 2 * GB_SZ)
#define G_SMEM_BYTES  (G_SMEM_FLOATS * 4)   // 55296

__global__ __launch_bounds__(256, 3)
void gemm_tf32_bias(const float* __restrict__ A, const float* __restrict__ B,
                    const float* __restrict__ bias, float* __restrict__ C,
                    int M, int N, int K) {
    extern __shared__ float sg[];
    float* AsBase = sg;
    float* BsBase = sg + 2 * GA_SZ;

    const int tid  = threadIdx.x;
    const int warp = tid >> 5;
    const int lane = tid & 31;
    const int wm   = warp >> 1;      // 0..3
    const int wn   = warp & 1;       // 0..1
    const int g    = lane >> 2;
    const int tig  = lane & 3;
    const int m0   = blockIdx.y * BM;
    const int n0   = blockIdx.x * BN;

    const uint32_t smemA = (uint32_t)__cvta_generic_to_shared(AsBase);
    const uint32_t smemB = (uint32_t)__cvta_generic_to_shared(BsBase);

    float acc[2][4][4];
#pragma unroll
    for (int mt = 0; mt < 2; mt++)
#pragma unroll
        for (int nt = 0; nt < 4; nt++)
#pragma unroll
            for (int i = 0; i < 4; i++) acc[mt][nt][i] = 0.f;

    const int T = K / BK;

    auto stage = [&](int kt, int st) {
        // A: 128x32 = 1024 float4 slots, 4 per thread
#pragma unroll
        for (int i = 0; i < 4; i++) {
            int pos = tid + i * 256;
            int r   = pos >> 3;              // 0..127
            int cv  = (pos & 7) * 4;         // 0..28
            uint32_t dst = smemA + (uint32_t)((st * GA_SZ + r * GA_STR + cv) << 2);
            const float* src = A + (size_t)(m0 + r) * K + kt + cv;
            int sz = (m0 + r < M) ? 16 : 0;
            asm volatile("cp.async.cg.shared.global [%0], [%1], 16, %2;\n"
                         :: "r"(dst), "l"(src), "r"(sz));
        }
        // B: 32x64 = 512 float4 slots, 2 per thread
#pragma unroll
        for (int i = 0; i < 2; i++) {
            int pos = tid + i * 256;
            int r   = pos >> 4;              // 0..31
            int cv  = (pos & 15) * 4;        // 0..60
            uint32_t dst = smemB + (uint32_t)((st * GB_SZ + r * GB_STR + cv) << 2);
            const float* src = B + (size_t)(kt + r) * N + n0 + cv;
            asm volatile("cp.async.cg.shared.global [%0], [%1], 16, 16;\n"
                         :: "r"(dst), "l"(src));
        }
        asm volatile("cp.async.commit_group;\n");
    };

    stage(0, 0);

    for (int kt = 0; kt < T; kt++) {
        const int st = kt & 1;
        if (kt + 1 < T) {
            stage((kt + 1) * BK, (kt + 1) & 1);
            asm volatile("cp.async.wait_group 1;\n");
        } else {
            asm volatile("cp.async.wait_group 0;\n");
        }
        __syncthreads();

        const float* As = AsBase + st * GA_SZ;
        const float* Bs = BsBase + st * GB_SZ;

#pragma unroll
        for (int ks = 0; ks < 4; ks++) {
            const int kb = ks * 8;
            uint32_t a[2][4];
#pragma unroll
            for (int mt = 0; mt < 2; mt++) {
                const int row = wm * 32 + mt * 16;
                a[mt][0] = __float_as_uint(As[(row + g    ) * GA_STR + kb + tig    ]);
                a[mt][1] = __float_as_uint(As[(row + g + 8) * GA_STR + kb + tig    ]);
                a[mt][2] = __float_as_uint(As[(row + g    ) * GA_STR + kb + tig + 4]);
                a[mt][3] = __float_as_uint(As[(row + g + 8) * GA_STR + kb + tig + 4]);
            }
            uint32_t b[4][2];
#pragma unroll
            for (int nt = 0; nt < 4; nt++) {
                const int col = wn * 32 + nt * 8 + g;
                b[nt][0] = __float_as_uint(Bs[(kb + tig    ) * GB_STR + col]);
                b[nt][1] = __float_as_uint(Bs[(kb + tig + 4) * GB_STR + col]);
            }
#pragma unroll
            for (int mt = 0; mt < 2; mt++)
#pragma unroll
                for (int nt = 0; nt < 4; nt++)
                    mma_tf32(acc[mt][nt], a[mt], b[nt]);
        }
        __syncthreads();
    }

#pragma unroll
    for (int mt = 0; mt < 2; mt++) {
        const int row0 = m0 + wm * 32 + mt * 16 + g;
#pragma unroll
        for (int nt = 0; nt < 4; nt++) {
            const int col = n0 + wn * 32 + nt * 8 + tig * 2;
            const float2 bv = *(const float2*)(bias + col);
            if (row0 < M) {
                float2 r0 = make_float2(acc[mt][nt][0] + bv.x, acc[mt][nt][1] + bv.y);
                *(float2*)(C + (size_t)row0 * N + col) = r0;
            }
            if (row0 + 8 < M) {
                float2 r1 = make_float2(acc[mt][nt][2] + bv.x, acc[mt][nt][3] + bv.y);
                *(float2*)(C + (size_t)(row0 + 8) * N + col) = r1;
            }
        }
    }
}

// ---------------------------------------------------------------------------
// Kernel L: logits + bias + softmax -> probs in g_at. (unchanged)
// ---------------------------------------------------------------------------
#define KS_STR 68
#define T_STR  36

#define L_KS    0
#define L_QT    (L_KS  + 200 * KS_STR)
#define L_RPHT  (L_QT  + 64 * KS_STR)
#define L_RPWT  (L_RPHT + 64 * T_STR)
#define L_TH    (L_RPWT + 64 * T_STR)
#define L_TW    (L_TH  + 64 * T_STR)
#define L_REDA  (L_TW  + 64 * T_STR)
#define L_REDB  (L_REDA + 128)
#define L_QHW   (L_REDB + 128)
#define L_SMEM_FLOATS (L_QHW + 128)
#define L_SMEM_BYTES  (L_SMEM_FLOATS * 4)

__global__ __launch_bounds__(256, 2)
void attn_logits_kernel(const float* __restrict__ qkv,
                        const float* __restrict__ rph,
                        const float* __restrict__ rpw,
                        float* __restrict__ at_g) {
    extern __shared__ float sm[];
    float* Ks   = sm + L_KS;
    float* Qt   = sm + L_QT;
    float* rphT = sm + L_RPHT;
    float* rpwT = sm + L_RPWT;
    float* Th   = sm + L_TH;
    float* Tw   = sm + L_TW;
    float* redA = sm + L_REDA;
    float* redB = sm + L_REDB;
    int*   qhw  = (int*)(sm + L_QHW);

    const int blk  = blockIdx.x;
    const int bh   = blk >> 2;
    const int qb   = blk & 3;
    const int b    = bh / NH;
    const int h    = bh % NH;
    const int qbase = qb * 64;
    const int tid  = threadIdx.x;
    const int warp = tid >> 5;
    const int lane = tid & 31;
    const int g    = lane >> 2;
    const int tig  = lane & 3;
    const int wm   = warp >> 1;
    const int wn   = warp & 1;
    const float scale = 0.125f;

    const float* qkv_b = qkv + (size_t)b * HW * QKV_N;

    for (int idx = tid; idx < 64 * T_STR; idx += 256) {
        int d = idx / T_STR;
        int j = idx % T_STR;
        rphT[d * T_STR + j] = (j < 2 * S_DIM - 1) ? f2tf32(rph[j * HD + d]) : 0.f;
        rpwT[d * T_STR + j] = (j < 2 * S_DIM - 1) ? f2tf32(rpw[j * HD + d]) : 0.f;
    }
    for (int slot = tid; slot < 200 * 16; slot += 256) {
        int s  = slot >> 4;
        int d4 = (slot & 15) << 2;
        float4 v = make_float4(0.f, 0.f, 0.f, 0.f);
        if (s < HW) {
            v = *(const float4*)(qkv_b + (size_t)s * QKV_N + C_DIM + h * HD + d4);
            v.x = f2tf32(v.x); v.y = f2tf32(v.y); v.z = f2tf32(v.z); v.w = f2tf32(v.w);
        }
        *(float4*)&Ks[s * KS_STR + d4] = v;
    }
    for (int slot = tid; slot < 64 * 16; slot += 256) {
        int ql = slot >> 4;
        int d4 = (slot & 15) << 2;
        int s  = qbase + ql;
        float4 v = make_float4(0.f, 0.f, 0.f, 0.f);
        if (s < HW) {
            v = *(const float4*)(qkv_b + (size_t)s * QKV_N + h * HD + d4);
            v.x = f2tf32(v.x); v.y = f2tf32(v.y); v.z = f2tf32(v.z); v.w = f2tf32(v.w);
        }
        *(float4*)&Qt[ql * KS_STR + d4] = v;
    }
    if (tid < 64) {
        int s = qbase + tid;
        qhw[tid]      = s / S_DIM;
        qhw[64 + tid] = s % S_DIM;
    }
    __syncthreads();

    const int rB = wm * 16;
    uint32_t af[8][4];
#pragma unroll
    for (int kc = 0; kc < 8; kc++) {
        const int kb = kc * 8;
        af[kc][0] = __float_as_uint(Qt[(rB + g    ) * KS_STR + kb + tig    ]);
        af[kc][1] = __float_as_uint(Qt[(rB + g + 8) * KS_STR + kb + tig    ]);
        af[kc][2] = __float_as_uint(Qt[(rB + g    ) * KS_STR + kb + tig + 4]);
        af[kc][3] = __float_as_uint(Qt[(rB + g + 8) * KS_STR + kb + tig + 4]);
    }

    {
        const float* Bt = wn ? rpwT : rphT;
        float*       Dt = wn ? Tw   : Th;
#pragma unroll
        for (int nt = 0; nt < 4; nt++) {
            float acc[4] = {0.f, 0.f, 0.f, 0.f};
            const int col = nt * 8 + g;
#pragma unroll
            for (int kc = 0; kc < 8; kc++) {
                const int kb = kc * 8;
                uint32_t bf[2];
                bf[0] = __float_as_uint(Bt[(kb + tig    ) * T_STR + col]);
                bf[1] = __float_as_uint(Bt[(kb + tig + 4) * T_STR + col]);
                mma_tf32(acc, af[kc], bf);
            }
            const int c0 = nt * 8 + 2 * tig;
            Dt[(rB + g    ) * T_STR + c0    ] = acc[0];
            Dt[(rB + g    ) * T_STR + c0 + 1] = acc[1];
            Dt[(rB + g + 8) * T_STR + c0    ] = acc[2];
            Dt[(rB + g + 8) * T_STR + c0 + 1] = acc[3];
        }
    }
    __syncthreads();

    const int r0 = rB + g;
    const int r1 = r0 + 8;
    const int qh0 = qhw[r0],      qw0 = qhw[64 + r0];
    const int qh1 = qhw[r1],      qw1 = qhw[64 + r1];
    float lg[13][4];
#pragma unroll
    for (int it = 0; it < 13; it++) {
        const int nt  = wn * 13 + it;
        float acc[4] = {0.f, 0.f, 0.f, 0.f};
        const int col = nt * 8 + g;
#pragma unroll
        for (int kc = 0; kc < 8; kc++) {
            const int kb = kc * 8;
            uint32_t bf[2];
            bf[0] = __float_as_uint(Ks[col * KS_STR + kb + tig    ]);
            bf[1] = __float_as_uint(Ks[col * KS_STR + kb + tig + 4]);
            mma_tf32(acc, af[kc], bf);
        }
        const int c0 = nt * 8 + 2 * tig;
        const int c1 = c0 + 1;
        if (c0 < HW) {
            int kh = c0 / S_DIM, kw = c0 % S_DIM;
            lg[it][0] = acc[0] * scale + Th[r0 * T_STR + qh0 - kh + 13] + Tw[r0 * T_STR + qw0 - kw + 13];
            lg[it][2] = acc[2] * scale + Th[r1 * T_STR + qh1 - kh + 13] + Tw[r1 * T_STR + qw1 - kw + 13];
        } else { lg[it][0] = -1e30f; lg[it][2] = -1e30f; }
        if (c1 < HW) {
            int kh = c1 / S_DIM, kw = c1 % S_DIM;
            lg[it][1] = acc[1] * scale + Th[r0 * T_STR + qh0 - kh + 13] + Tw[r0 * T_STR + qw0 - kw + 13];
            lg[it][3] = acc[3] * scale + Th[r1 * T_STR + qh1 - kh + 13] + Tw[r1 * T_STR + qw1 - kw + 13];
        } else { lg[it][1] = -1e30f; lg[it][3] = -1e30f; }
    }

    float m0 = -1e30f, m1 = -1e30f;
#pragma unroll
    for (int it = 0; it < 13; it++) {
        m0 = fmaxf(m0, fmaxf(lg[it][0], lg[it][1]));
        m1 = fmaxf(m1, fmaxf(lg[it][2], lg[it][3]));
    }
    m0 = fmaxf(m0, __shfl_xor_sync(0xffffffffu, m0, 1));
    m0 = fmaxf(m0, __shfl_xor_sync(0xffffffffu, m0, 2));
    m1 = fmaxf(m1, __shfl_xor_sync(0xffffffffu, m1, 1));
    m1 = fmaxf(m1, __shfl_xor_sync(0xffffffffu, m1, 2));
    if (tig == 0) { redA[wn * 64 + r0] = m0; redA[wn * 64 + r1] = m1; }
    __syncthreads();
    const float M0 = fmaxf(redA[r0], redA[64 + r0]);
    const float M1 = fmaxf(redA[r1], redA[64 + r1]);

    float s0 = 0.f, s1 = 0.f;
#pragma unroll
    for (int it = 0; it < 13; it++) {
        float e0 = __expf(lg[it][0] - M0); lg[it][0] = e0; s0 += e0;
        float e1 = __expf(lg[it][1] - M0); lg[it][1] = e1; s0 += e1;
        float e2 = __expf(lg[it][2] - M1); lg[it][2] = e2; s1 += e2;
        float e3 = __expf(lg[it][3] - M1); lg[it][3] = e3; s1 += e3;
    }
    s0 += __shfl_xor_sync(0xffffffffu, s0, 1);
    s0 += __shfl_xor_sync(0xffffffffu, s0, 2);
    s1 += __shfl_xor_sync(0xffffffffu, s1, 1);
    s1 += __shfl_xor_sync(0xffffffffu, s1, 2);
    if (tig == 0) { redB[wn * 64 + r0] = s0; redB[wn * 64 + r1] = s1; }
    __syncthreads();
    const float inv0 = 1.0f / (redB[r0] + redB[64 + r0]);
    const float inv1 = 1.0f / (redB[r1] + redB[64 + r1]);

    const int row0 = qbase + r0;
    const int row1 = qbase + r1;
    float* atr0 = at_g + ((size_t)bh * HW + row0) * 200;
    float* atr1 = at_g + ((size_t)bh * HW + row1) * 200;
#pragma unroll
    for (int it = 0; it < 13; it++) {
        const int nt = wn * 13 + it;
        const int c0 = nt * 8 + 2 * tig;
        if (c0 < HW) {
            if (row0 < HW) {
                float2 p = make_float2(f2tf32(lg[it][0] * inv0), f2tf32(lg[it][1] * inv0));
                *(float2*)(atr0 + c0) = p;
            }
            if (row1 < HW) {
                float2 p = make_float2(f2tf32(lg[it][2] * inv1), f2tf32(lg[it][3] * inv1));
                *(float2*)(atr1 + c0) = p;
            }
        }
    }
}

// ---------------------------------------------------------------------------
// Kernel V: out = probs @ V. ctx stored tf32-rounded. (unchanged)
// ---------------------------------------------------------------------------
#define V_STR  72
#define AT_STR 204
#define V_SMEM_FLOATS (200 * V_STR + 64 * AT_STR)
#define V_SMEM_BYTES  (V_SMEM_FLOATS * 4)

__global__ __launch_bounds__(256, 2)
void attn_av_kernel(const float* __restrict__ qkv,
                    const float* __restrict__ at_g,
                    float* __restrict__ ctx) {
    extern __shared__ float sm[];
    float* Vs  = sm;
    float* atS = sm + 200 * V_STR;

    const int bh   = blockIdx.x;
    const int b    = bh / NH;
    const int h    = bh % NH;
    const int tid  = threadIdx.x;
    const int warp = tid >> 5;
    const int lane = tid & 31;
    const int g    = lane >> 2;
    const int tig  = lane & 3;
    const int wm   = warp >> 1;
    const int wn   = warp & 1;

    const float* qkv_b = qkv + (size_t)b * HW * QKV_N;
    const float* at_b  = at_g + (size_t)bh * HW * 200;

    for (int slot = tid; slot < 200 * 16; slot += 256) {
        int s  = slot >> 4;
        int d4 = (slot & 15) << 2;
        float4 v = make_float4(0.f, 0.f, 0.f, 0.f);
        if (s < HW) {
            v = *(const float4*)(qkv_b + (size_t)s * QKV_N + 2 * C_DIM + h * HD + d4);
            v.x = f2tf32(v.x); v.y = f2tf32(v.y); v.z = f2tf32(v.z); v.w = f2tf32(v.w);
        }
        *(float4*)&Vs[s * V_STR + d4] = v;
    }

    for (int qb = 0; qb < 4; qb++) {
        const int qbase = qb * 64;
        __syncthreads();

        for (int slot = tid; slot < 64 * 50; slot += 256) {
            int rr = slot / 50;
            int c4 = slot % 50;
            int s  = qbase + rr;
            float4 v = make_float4(0.f, 0.f, 0.f, 0.f);
            if (s < HW && c4 < 49)
                v = *(const float4*)(at_b + (size_t)s * 200 + c4 * 4);
            *(float4*)&atS[rr * AT_STR + c4 * 4] = v;
        }
        __syncthreads();

        const int rB = wm * 16;
        float acc[4][4];
#pragma unroll
        for (int nt = 0; nt < 4; nt++)
#pragma unroll
            for (int i = 0; i < 4; i++) acc[nt][i] = 0.f;

        for (int kc = 0; kc < 25; kc++) {
            const int kb = kc * 8;
            uint32_t a[4];
            a[0] = __float_as_uint(atS[(rB + g    ) * AT_STR + kb + tig    ]);
            a[1] = __float_as_uint(atS[(rB + g + 8) * AT_STR + kb + tig    ]);
            a[2] = __float_as_uint(atS[(rB + g    ) * AT_STR + kb + tig + 4]);
            a[3] = __float_as_uint(atS[(rB + g + 8) * AT_STR + kb + tig + 4]);
#pragma unroll
            for (int nt = 0; nt < 4; nt++) {
                const int col = wn * 32 + nt * 8 + g;
                uint32_t bf[2];
                bf[0] = __float_as_uint(Vs[(kb + tig    ) * V_STR + col]);
                bf[1] = __float_as_uint(Vs[(kb + tig + 4) * V_STR + col]);
                mma_tf32(acc[nt], a, bf);
            }
        }

        const int s0 = qbase + rB + g;
        const int s1 = s0 + 8;
#pragma unroll
        for (int nt = 0; nt < 4; nt++) {
            const int d = wn * 32 + nt * 8 + 2 * tig;
            if (s0 < HW) {
                float2 r0 = make_float2(f2tf32(acc[nt][0]), f2tf32(acc[nt][1]));
                *(float2*)(ctx + (size_t)(b * HW + s0) * C_DIM + h * HD + d) = r0;
            }
            if (s1 < HW) {
                float2 r1 = make_float2(f2tf32(acc[nt][2]), f2tf32(acc[nt][3]));
                *(float2*)(ctx + (size_t)(b * HW + s1) * C_DIM + h * HD + d) = r1;
            }
        }
    }
}

// ---------------------------------------------------------------------------
extern "C" void kernel_launch(void* const* d_in, const int* in_sizes, int n_in,
                              void* d_out, int out_size) {
    const float* x      = (const float*)d_in[0];
    const float* w_qkv  = (const float*)d_in[1];
    const float* b_qkv  = (const float*)d_in[2];
    const float* w_proj = (const float*)d_in[3];
    const float* b_proj = (const float*)d_in[4];
    const float* rph    = (const float*)d_in[5];
    const float* rpw    = (const float*)d_in[6];
    float* out = (float*)d_out;

    float *qkv_ptr, *ctx_ptr, *at_ptr, *xc_ptr, *wq_ptr, *wp_ptr;
    cudaGetSymbolAddress((void**)&qkv_ptr, g_qkv);
    cudaGetSymbolAddress((void**)&ctx_ptr, g_ctx);
    cudaGetSymbolAddress((void**)&at_ptr, g_at);
    cudaGetSymbolAddress((void**)&xc_ptr, g_xc);
    cudaGetSymbolAddress((void**)&wq_ptr, g_wqkv);
    cudaGetSymbolAddress((void**)&wp_ptr, g_wproj);

    static bool attr_set = false;
    if (!attr_set) {
        cudaFuncSetAttribute(gemm_tf32_bias,
                             cudaFuncAttributeMaxDynamicSharedMemorySize,
                             G_SMEM_BYTES);
        cudaFuncSetAttribute(attn_logits_kernel,
                             cudaFuncAttributeMaxDynamicSharedMemorySize,
                             L_SMEM_BYTES);
        cudaFuncSetAttribute(attn_av_kernel,
                             cudaFuncAttributeMaxDynamicSharedMemorySize,
                             V_SMEM_BYTES);
        attr_set = true;
    }

    // 0) Pre-round GEMM operands to tf32 (once)
    cvt_tf32_kernel<<<592, 256>>>(x, xc_ptr, M_TOK * C_DIM / 4);
    cvt_tf32_kernel<<<148, 256>>>(w_qkv, wq_ptr, C_DIM * QKV_N / 4);
    cvt_tf32_kernel<<<148, 256>>>(w_proj, wp_ptr, C_DIM * C_DIM / 4);

    // 1) QKV projection
    {
        dim3 grid(QKV_N / BN, (M_TOK + BM - 1) / BM);   // 36 x 307
        gemm_tf32_bias<<<grid, 256, G_SMEM_BYTES>>>(xc_ptr, wq_ptr, b_qkv, qkv_ptr,
                                                    M_TOK, QKV_N, C_DIM);
    }

    // 2a) Logits + bias + softmax -> probs
    attn_logits_kernel<<<NHEADS_TOT * 4, 256, L_SMEM_BYTES>>>(qkv_ptr, rph, rpw, at_ptr);

    // 2b) AV (ctx written tf32-rounded)
    attn_av_kernel<<<NHEADS_TOT, 256, V_SMEM_BYTES>>>(qkv_ptr, at_ptr, ctx_ptr);

    // 3) Output projection
    {
        dim3 grid(C_DIM / BN, (M_TOK + BM - 1) / BM);   // 12 x 307
        gemm_tf32_bias<<<grid, 256, G_SMEM_BYTES>>>(ctx_ptr, wp_ptr, b_proj, out,
                                                    M_TOK, C_DIM, C_DIM);
    }
}

// round 9
// speedup vs baseline: 1.1536x; 1.1536x over previous
#include <cuda_runtime.h>
#include <cstdint>
#include <cstddef>

// Problem constants
#define B_WIN  200
#define S_DIM  14
#define HW     196           // 14*14
#define C_DIM  768
#define NH     12
#define HD     64
#define M_TOK  (B_WIN * HW)  // 39200
#define QKV_N  (3 * C_DIM)   // 2304
#define NHEADS_TOT (B_WIN * NH)   // 2400

// Scratch (device globals: allocation-free per harness rules)
__device__ float g_qkv[(size_t)M_TOK * QKV_N];          // (B*HW, 2304)
__device__ float g_ctx[(size_t)M_TOK * C_DIM];          // (B*HW, 768) tf32-rounded
__device__ float g_at[(size_t)NHEADS_TOT * HW * 200];   // probs (tf32), row stride 200
__device__ float g_xc[(size_t)M_TOK * C_DIM];           // x, tf32-rounded
__device__ float g_wqkvT[(size_t)QKV_N * C_DIM];        // w_qkv^T [N][K], tf32-rounded
__device__ float g_wprojT[(size_t)C_DIM * C_DIM];       // w_proj^T [N][K], tf32-rounded

// ---------------------------------------------------------------------------
// tf32 helpers
// ---------------------------------------------------------------------------
__device__ __forceinline__ float f2tf32(float x) {
    uint32_t r;
    asm("cvt.rna.tf32.f32 %0, %1;" : "=r"(r) : "f"(x));
    return __uint_as_float(r);
}

__device__ __forceinline__ void mma_tf32(float* c, const uint32_t* a, const uint32_t* b) {
    asm volatile(
        "mma.sync.aligned.m16n8k8.row.col.f32.tf32.tf32.f32 "
        "{%0,%1,%2,%3}, {%4,%5,%6,%7}, {%8,%9}, {%0,%1,%2,%3};"
        : "+f"(c[0]), "+f"(c[1]), "+f"(c[2]), "+f"(c[3])
        : "r"(a[0]), "r"(a[1]), "r"(a[2]), "r"(a[3]),
          "r"(b[0]), "r"(b[1]));
}

__device__ __forceinline__ void ldsm_x4(uint32_t& r0, uint32_t& r1,
                                        uint32_t& r2, uint32_t& r3, uint32_t addr) {
    asm volatile("ldmatrix.sync.aligned.m8n8.x4.shared.b16 {%0,%1,%2,%3}, [%4];"
                 : "=r"(r0), "=r"(r1), "=r"(r2), "=r"(r3) : "r"(addr));
}

// ---------------------------------------------------------------------------
// Pre-pass 1: tf32-round a buffer (float4 grid-stride).
// ---------------------------------------------------------------------------
__global__ void cvt_tf32_kernel(const float* __restrict__ src,
                                float* __restrict__ dst, int n4) {
    int i = blockIdx.x * blockDim.x + threadIdx.x;
    int stride = gridDim.x * blockDim.x;
    for (; i < n4; i += stride) {
        float4 v = *(const float4*)(src + (size_t)i * 4);
        v.x = f2tf32(v.x); v.y = f2tf32(v.y); v.z = f2tf32(v.z); v.w = f2tf32(v.w);
        *(float4*)(dst + (size_t)i * 4) = v;
    }
}

// ---------------------------------------------------------------------------
// Pre-pass 2: transpose + tf32-round. src [K][N] -> dst [N][K].
// block (32,8), grid (N/32, K/32). K,N multiples of 32.
// ---------------------------------------------------------------------------
__global__ void transpose_tf32_kernel(const float* __restrict__ src,
                                      float* __restrict__ dst, int K, int N) {
    __shared__ float t[32][33];
    const int nb = blockIdx.x * 32;
    const int kb = blockIdx.y * 32;
    const int tx = threadIdx.x, ty = threadIdx.y;
#pragma unroll
    for (int i = 0; i < 32; i += 8)
        t[ty + i][tx] = f2tf32(src[(size_t)(kb + ty + i) * N + nb + tx]);
    __syncthreads();
#pragma unroll
    for (int i = 0; i < 32; i += 8)
        dst[(size_t)(nb + ty + i) * K + kb + tx] = t[tx][ty + i];
}

// ---------------------------------------------------------------------------
// Tensor-core tf32 GEMM (transposed-operand form), cp.async double-buffered,
// ldmatrix fragment loads. C[M][N] = X[M][K] @ W[K][N] + bias, where the
// kernel receives WT = W^T [N][K] (pre-transposed, tf32-rounded).
// mma A-operand = WT tile (16n x 8k), B-operand = X tile (8k x 8m),
// D = (n x m) = C^T fragments.
// BM(m)=128, BN(n)=128, BK=32. 256 thr = 8 warps: 4 on n (32) x 2 on m (64).
// ---------------------------------------------------------------------------
#define BMT 128
#define BNT 128
#define BKT 32
#define XW_STR 36
#define TILE_SZ (128 * XW_STR)            // floats per (X or W) stage
#define G_SMEM_FLOATS (4 * TILE_SZ)       // X[2] + W[2]
#define G_SMEM_BYTES  (G_SMEM_FLOATS * 4) // 73728

__global__ __launch_bounds__(256, 2)
void gemm_tf32_bias_t(const float* __restrict__ X,   // [M][K] tf32-rounded
                      const float* __restrict__ WT,  // [N][K] tf32-rounded
                      const float* __restrict__ bias,
                      float* __restrict__ C,
                      int M, int N, int K) {
    extern __shared__ float sg[];
    float* XsBase = sg;                 // [2][128][36]
    float* WsBase = sg + 2 * TILE_SZ;   // [2][128][36]

    const int tid  = threadIdx.x;
    const int warp = tid >> 5;
    const int lane = tid & 31;
    const int g    = lane >> 2;
    const int tig  = lane & 3;
    const int wtn  = warp >> 1;      // 0..3 : n-offset 32
    const int wtm  = warp & 1;       // 0..1 : m-offset 64
    const int m0   = blockIdx.y * BMT;
    const int n0   = blockIdx.x * BNT;

    const uint32_t smemX = (uint32_t)__cvta_generic_to_shared(XsBase);
    const uint32_t smemW = (uint32_t)__cvta_generic_to_shared(WsBase);

    // ldmatrix per-lane source coords
    // A (W^T tile): matrices ordered (rows0-7,kb),(rows8-15,kb),(rows0-7,kb+4),(rows8-15,kb+4)
    const int lrA = (lane & 7) + ((lane >> 3) & 1) * 8;
    const int lcA = (lane >> 4) * 4;
    // B (X tile): matrices ordered (rows0-7,kb),(rows0-7,kb+4),(rows8-15,kb),(rows8-15,kb+4)
    const int lrB = (lane & 7) + (lane >> 4) * 8;
    const int lcB = ((lane >> 3) & 1) * 4;

    const uint32_t aBase = smemW + (uint32_t)(((wtn * 32 + lrA) * XW_STR + lcA) << 2);
    const uint32_t bBase = smemX + (uint32_t)(((wtm * 64 + lrB) * XW_STR + lcB) << 2);

    float acc[2][8][4];
#pragma unroll
    for (int i = 0; i < 2; i++)
#pragma unroll
        for (int j = 0; j < 8; j++)
#pragma unroll
            for (int q = 0; q < 4; q++) acc[i][j][q] = 0.f;

    const int T = K / BKT;

    auto stage = [&](int kt, int st) {
        // X: 128 rows (m) x 32 k  = 1024 float4 slots, 4/thread
#pragma unroll
        for (int i = 0; i < 4; i++) {
            int pos = tid + i * 256;
            int r   = pos >> 3;
            int cv  = (pos & 7) * 4;
            uint32_t dst = smemX + (uint32_t)((st * TILE_SZ + r * XW_STR + cv) << 2);
            const float* src = X + (size_t)(m0 + r) * K + kt + cv;
            int sz = (m0 + r < M) ? 16 : 0;
            asm volatile("cp.async.cg.shared.global [%0], [%1], 16, %2;\n"
                         :: "r"(dst), "l"(src), "r"(sz));
        }
        // W^T: 128 rows (n) x 32 k
#pragma unroll
        for (int i = 0; i < 4; i++) {
            int pos = tid + i * 256;
            int r   = pos >> 3;
            int cv  = (pos & 7) * 4;
            uint32_t dst = smemW + (uint32_t)((st * TILE_SZ + r * XW_STR + cv) << 2);
            const float* src = WT + (size_t)(n0 + r) * K + kt + cv;
            asm volatile("cp.async.cg.shared.global [%0], [%1], 16, 16;\n"
                         :: "r"(dst), "l"(src));
        }
        asm volatile("cp.async.commit_group;\n");
    };

    stage(0, 0);

    for (int kt = 0; kt < T; kt++) {
        const int st = kt & 1;
        if (kt + 1 < T) {
            stage((kt + 1) * BKT, (kt + 1) & 1);
            asm volatile("cp.async.wait_group 1;\n");
        } else {
            asm volatile("cp.async.wait_group 0;\n");
        }
        __syncthreads();

        const uint32_t stOff = (uint32_t)(st * TILE_SZ * 4);

#pragma unroll
        for (int ks = 0; ks < 4; ks++) {
            const uint32_t kOff = (uint32_t)(ks * 8 * 4);
            uint32_t a[2][4];
#pragma unroll
            for (int i = 0; i < 2; i++)
                ldsm_x4(a[i][0], a[i][1], a[i][2], a[i][3],
                        aBase + stOff + (uint32_t)(i * 16 * XW_STR * 4) + kOff);
            uint32_t b[8][2];
#pragma unroll
            for (int j2 = 0; j2 < 4; j2++)
                ldsm_x4(b[2 * j2][0], b[2 * j2][1], b[2 * j2 + 1][0], b[2 * j2 + 1][1],
                        bBase + stOff + (uint32_t)(j2 * 16 * XW_STR * 4) + kOff);
#pragma unroll
            for (int i = 0; i < 2; i++)
#pragma unroll
                for (int j = 0; j < 8; j++)
                    mma_tf32(acc[i][j], a[i], b[j]);
        }
        __syncthreads();
    }

    // Epilogue: acc[i][j] = D(n x m): c0=(n=g, m=2tig), c1=(g,2tig+1),
    // c2=(g+8,2tig), c3=(g+8,2tig+1). Write C[m][n] + bias[n].
#pragma unroll
    for (int i = 0; i < 2; i++) {
        const int na = n0 + wtn * 32 + i * 16 + g;
        const int nb = na + 8;
        const float bva = bias[na];
        const float bvb = bias[nb];
#pragma unroll
        for (int j = 0; j < 8; j++) {
            const int ma = m0 + wtm * 64 + j * 8 + 2 * tig;
            if (ma < M) {
                C[(size_t)ma * N + na] = acc[i][j][0] + bva;
                C[(size_t)ma * N + nb] = acc[i][j][2] + bvb;
            }
            if (ma + 1 < M) {
                C[(size_t)(ma + 1) * N + na] = acc[i][j][1] + bva;
                C[(size_t)(ma + 1) * N + nb] = acc[i][j][3] + bvb;
            }
        }
    }
}

// ---------------------------------------------------------------------------
// Kernel L: logits + bias + softmax -> probs in g_at. (unchanged)
// ---------------------------------------------------------------------------
#define KS_STR 68
#define T_STR  36

#define L_KS    0
#define L_QT    (L_KS  + 200 * KS_STR)
#define L_RPHT  (L_QT  + 64 * KS_STR)
#define L_RPWT  (L_RPHT + 64 * T_STR)
#define L_TH    (L_RPWT + 64 * T_STR)
#define L_TW    (L_TH  + 64 * T_STR)
#define L_REDA  (L_TW  + 64 * T_STR)
#define L_REDB  (L_REDA + 128)
#define L_QHW   (L_REDB + 128)
#define L_SMEM_FLOATS (L_QHW + 128)
#define L_SMEM_BYTES  (L_SMEM_FLOATS * 4)

__global__ __launch_bounds__(256, 2)
void attn_logits_kernel(const float* __restrict__ qkv,
                        const float* __restrict__ rph,
                        const float* __restrict__ rpw,
                        float* __restrict__ at_g) {
    extern __shared__ float sm[];
    float* Ks   = sm + L_KS;
    float* Qt   = sm + L_QT;
    float* rphT = sm + L_RPHT;
    float* rpwT = sm + L_RPWT;
    float* Th   = sm + L_TH;
    float* Tw   = sm + L_TW;
    float* redA = sm + L_REDA;
    float* redB = sm + L_REDB;
    int*   qhw  = (int*)(sm + L_QHW);

    const int blk  = blockIdx.x;
    const int bh   = blk >> 2;
    const int qb   = blk & 3;
    const int b    = bh / NH;
    const int h    = bh % NH;
    const int qbase = qb * 64;
    const int tid  = threadIdx.x;
    const int warp = tid >> 5;
    const int lane = tid & 31;
    const int g    = lane >> 2;
    const int tig  = lane & 3;
    const int wm   = warp >> 1;
    const int wn   = warp & 1;
    const float scale = 0.125f;

    const float* qkv_b = qkv + (size_t)b * HW * QKV_N;

    for (int idx = tid; idx < 64 * T_STR; idx += 256) {
        int d = idx / T_STR;
        int j = idx % T_STR;
        rphT[d * T_STR + j] = (j < 2 * S_DIM - 1) ? f2tf32(rph[j * HD + d]) : 0.f;
        rpwT[d * T_STR + j] = (j < 2 * S_DIM - 1) ? f2tf32(rpw[j * HD + d]) : 0.f;
    }
    for (int slot = tid; slot < 200 * 16; slot += 256) {
        int s  = slot >> 4;
        int d4 = (slot & 15) << 2;
        float4 v = make_float4(0.f, 0.f, 0.f, 0.f);
        if (s < HW) {
            v = *(const float4*)(qkv_b + (size_t)s * QKV_N + C_DIM + h * HD + d4);
            v.x = f2tf32(v.x); v.y = f2tf32(v.y); v.z = f2tf32(v.z); v.w = f2tf32(v.w);
        }
        *(float4*)&Ks[s * KS_STR + d4] = v;
    }
    for (int slot = tid; slot < 64 * 16; slot += 256) {
        int ql = slot >> 4;
        int d4 = (slot & 15) << 2;
        int s  = qbase + ql;
        float4 v = make_float4(0.f, 0.f, 0.f, 0.f);
        if (s < HW) {
            v = *(const float4*)(qkv_b + (size_t)s * QKV_N + h * HD + d4);
            v.x = f2tf32(v.x); v.y = f2tf32(v.y); v.z = f2tf32(v.z); v.w = f2tf32(v.w);
        }
        *(float4*)&Qt[ql * KS_STR + d4] = v;
    }
    if (tid < 64) {
        int s = qbase + tid;
        qhw[tid]      = s / S_DIM;
        qhw[64 + tid] = s % S_DIM;
    }
    __syncthreads();

    const int rB = wm * 16;
    uint32_t af[8][4];
#pragma unroll
    for (int kc = 0; kc < 8; kc++) {
        const int kb = kc * 8;
        af[kc][0] = __float_as_uint(Qt[(rB + g    ) * KS_STR + kb + tig    ]);
        af[kc][1] = __float_as_uint(Qt[(rB + g + 8) * KS_STR + kb + tig    ]);
        af[kc][2] = __float_as_uint(Qt[(rB + g    ) * KS_STR + kb + tig + 4]);
        af[kc][3] = __float_as_uint(Qt[(rB + g + 8) * KS_STR + kb + tig + 4]);
    }

    {
        const float* Bt = wn ? rpwT : rphT;
        float*       Dt = wn ? Tw   : Th;
#pragma unroll
        for (int nt = 0; nt < 4; nt++) {
            float acc[4] = {0.f, 0.f, 0.f, 0.f};
            const int col = nt * 8 + g;
#pragma unroll
            for (int kc = 0; kc < 8; kc++) {
                const int kb = kc * 8;
                uint32_t bf[2];
                bf[0] = __float_as_uint(Bt[(kb + tig    ) * T_STR + col]);
                bf[1] = __float_as_uint(Bt[(kb + tig + 4) * T_STR + col]);
                mma_tf32(acc, af[kc], bf);
            }
            const int c0 = nt * 8 + 2 * tig;
            Dt[(rB + g    ) * T_STR + c0    ] = acc[0];
            Dt[(rB + g    ) * T_STR + c0 + 1] = acc[1];
            Dt[(rB + g + 8) * T_STR + c0    ] = acc[2];
            Dt[(rB + g + 8) * T_STR + c0 + 1] = acc[3];
        }
    }
    __syncthreads();

    const int r0 = rB + g;
    const int r1 = r0 + 8;
    const int qh0 = qhw[r0],      qw0 = qhw[64 + r0];
    const int qh1 = qhw[r1],      qw1 = qhw[64 + r1];
    float lg[13][4];
#pragma unroll
    for (int it = 0; it < 13; it++) {
        const int nt  = wn * 13 + it;
        float acc[4] = {0.f, 0.f, 0.f, 0.f};
        const int col = nt * 8 + g;
#pragma unroll
        for (int kc = 0; kc < 8; kc++) {
            const int kb = kc * 8;
            uint32_t bf[2];
            bf[0] = __float_as_uint(Ks[col * KS_STR + kb + tig    ]);
            bf[1] = __float_as_uint(Ks[col * KS_STR + kb + tig + 4]);
            mma_tf32(acc, af[kc], bf);
        }
        const int c0 = nt * 8 + 2 * tig;
        const int c1 = c0 + 1;
        if (c0 < HW) {
            int kh = c0 / S_DIM, kw = c0 % S_DIM;
            lg[it][0] = acc[0] * scale + Th[r0 * T_STR + qh0 - kh + 13] + Tw[r0 * T_STR + qw0 - kw + 13];
            lg[it][2] = acc[2] * scale + Th[r1 * T_STR + qh1 - kh + 13] + Tw[r1 * T_STR + qw1 - kw + 13];
        } else { lg[it][0] = -1e30f; lg[it][2] = -1e30f; }
        if (c1 < HW) {
            int kh = c1 / S_DIM, kw = c1 % S_DIM;
            lg[it][1] = acc[1] * scale + Th[r0 * T_STR + qh0 - kh + 13] + Tw[r0 * T_STR + qw0 - kw + 13];
            lg[it][3] = acc[3] * scale + Th[r1 * T_STR + qh1 - kh + 13] + Tw[r1 * T_STR + qw1 - kw + 13];
        } else { lg[it][1] = -1e30f; lg[it][3] = -1e30f; }
    }

    float m0 = -1e30f, m1 = -1e30f;
#pragma unroll
    for (int it = 0; it < 13; it++) {
        m0 = fmaxf(m0, fmaxf(lg[it][0], lg[it][1]));
        m1 = fmaxf(m1, fmaxf(lg[it][2], lg[it][3]));
    }
    m0 = fmaxf(m0, __shfl_xor_sync(0xffffffffu, m0, 1));
    m0 = fmaxf(m0, __shfl_xor_sync(0xffffffffu, m0, 2));
    m1 = fmaxf(m1, __shfl_xor_sync(0xffffffffu, m1, 1));
    m1 = fmaxf(m1, __shfl_xor_sync(0xffffffffu, m1, 2));
    if (tig == 0) { redA[wn * 64 + r0] = m0; redA[wn * 64 + r1] = m1; }
    __syncthreads();
    const float M0 = fmaxf(redA[r0], redA[64 + r0]);
    const float M1 = fmaxf(redA[r1], redA[64 + r1]);

    float s0 = 0.f, s1 = 0.f;
#pragma unroll
    for (int it = 0; it < 13; it++) {
        float e0 = __expf(lg[it][0] - M0); lg[it][0] = e0; s0 += e0;
        float e1 = __expf(lg[it][1] - M0); lg[it][1] = e1; s0 += e1;
        float e2 = __expf(lg[it][2] - M1); lg[it][2] = e2; s1 += e2;
        float e3 = __expf(lg[it][3] - M1); lg[it][3] = e3; s1 += e3;
    }
    s0 += __shfl_xor_sync(0xffffffffu, s0, 1);
    s0 += __shfl_xor_sync(0xffffffffu, s0, 2);
    s1 += __shfl_xor_sync(0xffffffffu, s1, 1);
    s1 += __shfl_xor_sync(0xffffffffu, s1, 2);
    if (tig == 0) { redB[wn * 64 + r0] = s0; redB[wn * 64 + r1] = s1; }
    __syncthreads();
    const float inv0 = 1.0f / (redB[r0] + redB[64 + r0]);
    const float inv1 = 1.0f / (redB[r1] + redB[64 + r1]);

    const int row0 = qbase + r0;
    const int row1 = qbase + r1;
    float* atr0 = at_g + ((size_t)bh * HW + row0) * 200;
    float* atr1 = at_g + ((size_t)bh * HW + row1) * 200;
#pragma unroll
    for (int it = 0; it < 13; it++) {
        const int nt = wn * 13 + it;
        const int c0 = nt * 8 + 2 * tig;
        if (c0 < HW) {
            if (row0 < HW) {
                float2 p = make_float2(f2tf32(lg[it][0] * inv0), f2tf32(lg[it][1] * inv0));
                *(float2*)(atr0 + c0) = p;
            }
            if (row1 < HW) {
                float2 p = make_float2(f2tf32(lg[it][2] * inv1), f2tf32(lg[it][3] * inv1));
                *(float2*)(atr1 + c0) = p;
            }
        }
    }
}

// ---------------------------------------------------------------------------
// Kernel V: out = probs @ V. ctx stored tf32-rounded. (unchanged)
// ---------------------------------------------------------------------------
#define V_STR  72
#define AT_STR 204
#define V_SMEM_FLOATS (200 * V_STR + 64 * AT_STR)
#define V_SMEM_BYTES  (V_SMEM_FLOATS * 4)

__global__ __launch_bounds__(256, 2)
void attn_av_kernel(const float* __restrict__ qkv,
                    const float* __restrict__ at_g,
                    float* __restrict__ ctx) {
    extern __shared__ float sm[];
    float* Vs  = sm;
    float* atS = sm + 200 * V_STR;

    const int bh   = blockIdx.x;
    const int b    = bh / NH;
    const int h    = bh % NH;
    const int tid  = threadIdx.x;
    const int warp = tid >> 5;
    const int lane = tid & 31;
    const int g    = lane >> 2;
    const int tig  = lane & 3;
    const int wm   = warp >> 1;
    const int wn   = warp & 1;

    const float* qkv_b = qkv + (size_t)b * HW * QKV_N;
    const float* at_b  = at_g + (size_t)bh * HW * 200;

    for (int slot = tid; slot < 200 * 16; slot += 256) {
        int s  = slot >> 4;
        int d4 = (slot & 15) << 2;
        float4 v = make_float4(0.f, 0.f, 0.f, 0.f);
        if (s < HW) {
            v = *(const float4*)(qkv_b + (size_t)s * QKV_N + 2 * C_DIM + h * HD + d4);
            v.x = f2tf32(v.x); v.y = f2tf32(v.y); v.z = f2tf32(v.z); v.w = f2tf32(v.w);
        }
        *(float4*)&Vs[s * V_STR + d4] = v;
    }

    for (int qb = 0; qb < 4; qb++) {
        const int qbase = qb * 64;
        __syncthreads();

        for (int slot = tid; slot < 64 * 50; slot += 256) {
            int rr = slot / 50;
            int c4 = slot % 50;
            int s  = qbase + rr;
            float4 v = make_float4(0.f, 0.f, 0.f, 0.f);
            if (s < HW && c4 < 49)
                v = *(const float4*)(at_b + (size_t)s * 200 + c4 * 4);
            *(float4*)&atS[rr * AT_STR + c4 * 4] = v;
        }
        __syncthreads();

        const int rB = wm * 16;
        float acc[4][4];
#pragma unroll
        for (int nt = 0; nt < 4; nt++)
#pragma unroll
            for (int i = 0; i < 4; i++) acc[nt][i] = 0.f;

        for (int kc = 0; kc < 25; kc++) {
            const int kb = kc * 8;
            uint32_t a[4];
            a[0] = __float_as_uint(atS[(rB + g    ) * AT_STR + kb + tig    ]);
            a[1] = __float_as_uint(atS[(rB + g + 8) * AT_STR + kb + tig    ]);
            a[2] = __float_as_uint(atS[(rB + g    ) * AT_STR + kb + tig + 4]);
            a[3] = __float_as_uint(atS[(rB + g + 8) * AT_STR + kb + tig + 4]);
#pragma unroll
            for (int nt = 0; nt < 4; nt++) {
                const int col = wn * 32 + nt * 8 + g;
                uint32_t bf[2];
                bf[0] = __float_as_uint(Vs[(kb + tig    ) * V_STR + col]);
                bf[1] = __float_as_uint(Vs[(kb + tig + 4) * V_STR + col]);
                mma_tf32(acc[nt], a, bf);
            }
        }

        const int s0 = qbase + rB + g;
        const int s1 = s0 + 8;
#pragma unroll
        for (int nt = 0; nt < 4; nt++) {
            const int d = wn * 32 + nt * 8 + 2 * tig;
            if (s0 < HW) {
                float2 r0 = make_float2(f2tf32(acc[nt][0]), f2tf32(acc[nt][1]));
                *(float2*)(ctx + (size_t)(b * HW + s0) * C_DIM + h * HD + d) = r0;
            }
            if (s1 < HW) {
                float2 r1 = make_float2(f2tf32(acc[nt][2]), f2tf32(acc[nt][3]));
                *(float2*)(ctx + (size_t)(b * HW + s1) * C_DIM + h * HD + d) = r1;
            }
        }
    }
}

// ---------------------------------------------------------------------------
extern "C" void kernel_launch(void* const* d_in, const int* in_sizes, int n_in,
                              void* d_out, int out_size) {
    const float* x      = (const float*)d_in[0];
    const float* w_qkv  = (const float*)d_in[1];
    const float* b_qkv  = (const float*)d_in[2];
    const float* w_proj = (const float*)d_in[3];
    const float* b_proj = (const float*)d_in[4];
    const float* rph    = (const float*)d_in[5];
    const float* rpw    = (const float*)d_in[6];
    float* out = (float*)d_out;

    float *qkv_ptr, *ctx_ptr, *at_ptr, *xc_ptr, *wqT_ptr, *wpT_ptr;
    cudaGetSymbolAddress((void**)&qkv_ptr, g_qkv);
    cudaGetSymbolAddress((void**)&ctx_ptr, g_ctx);
    cudaGetSymbolAddress((void**)&at_ptr, g_at);
    cudaGetSymbolAddress((void**)&xc_ptr, g_xc);
    cudaGetSymbolAddress((void**)&wqT_ptr, g_wqkvT);
    cudaGetSymbolAddress((void**)&wpT_ptr, g_wprojT);

    static bool attr_set = false;
    if (!attr_set) {
        cudaFuncSetAttribute(gemm_tf32_bias_t,
                             cudaFuncAttributeMaxDynamicSharedMemorySize,
                             G_SMEM_BYTES);
        cudaFuncSetAttribute(attn_logits_kernel,
                             cudaFuncAttributeMaxDynamicSharedMemorySize,
                             L_SMEM_BYTES);
        cudaFuncSetAttribute(attn_av_kernel,
                             cudaFuncAttributeMaxDynamicSharedMemorySize,
                             V_SMEM_BYTES);
        attr_set = true;
    }

    // 0) Pre-pass: tf32-round x; transpose + tf32-round weights
    cvt_tf32_kernel<<<592, 256>>>(x, xc_ptr, M_TOK * C_DIM / 4);
    {
        dim3 blk(32, 8);
        dim3 gq(QKV_N / 32, C_DIM / 32);   // src [768][2304]
        transpose_tf32_kernel<<<gq, blk>>>(w_qkv, wqT_ptr, C_DIM, QKV_N);
        dim3 gp(C_DIM / 32, C_DIM / 32);   // src [768][768]
        transpose_tf32_kernel<<<gp, blk>>>(w_proj, wpT_ptr, C_DIM, C_DIM);
    }

    // 1) QKV projection (ldmatrix + mma, cp.async double-buffered)
    {
        dim3 grid(QKV_N / BNT, (M_TOK + BMT - 1) / BMT);   // 18 x 307
        gemm_tf32_bias_t<<<grid, 256, G_SMEM_BYTES>>>(xc_ptr, wqT_ptr, b_qkv, qkv_ptr,
                                                      M_TOK, QKV_N, C_DIM);
    }

    // 2a) Logits + bias + softmax -> probs
    attn_logits_kernel<<<NHEADS_TOT * 4, 256, L_SMEM_BYTES>>>(qkv_ptr, rph, rpw, at_ptr);

    // 2b) AV (ctx written tf32-rounded)
    attn_av_kernel<<<NHEADS_TOT, 256, V_SMEM_BYTES>>>(qkv_ptr, at_ptr, ctx_ptr);

    // 3) Output projection
    {
        dim3 grid(C_DIM / BNT, (M_TOK + BMT - 1) / BMT);   // 6 x 307
        gemm_tf32_bias_t<<<grid, 256, G_SMEM_BYTES>>>(ctx_ptr, wpT_ptr, b_proj, out,
                                                      M_TOK, C_DIM, C_DIM);
    }
}

// round 10
// speedup vs baseline: 1.2482x; 1.0821x over previous
#include <cuda_runtime.h>
#include <cstdint>
#include <cstddef>

// Problem constants
#define B_WIN  200
#define S_DIM  14
#define HW     196           // 14*14
#define C_DIM  768
#define NH     12
#define HD     64
#define M_TOK  (B_WIN * HW)  // 39200
#define QKV_N  (3 * C_DIM)   // 2304
#define NHEADS_TOT (B_WIN * NH)   // 2400

// Scratch (device globals: allocation-free per harness rules)
__device__ float g_qkv[(size_t)M_TOK * QKV_N];          // (B*HW, 2304)
__device__ float g_ctx[(size_t)M_TOK * C_DIM];          // (B*HW, 768) tf32-rounded
__device__ float g_at[(size_t)NHEADS_TOT * HW * 200];   // probs (tf32), row stride 200
__device__ float g_xc[(size_t)M_TOK * C_DIM];           // x, tf32-rounded
__device__ float g_wqkvT[(size_t)QKV_N * C_DIM];        // w_qkv^T [N][K], tf32-rounded
__device__ float g_wprojT[(size_t)C_DIM * C_DIM];       // w_proj^T [N][K], tf32-rounded

// ---------------------------------------------------------------------------
// tf32 helpers
// ---------------------------------------------------------------------------
__device__ __forceinline__ float f2tf32(float x) {
    uint32_t r;
    asm("cvt.rna.tf32.f32 %0, %1;" : "=r"(r) : "f"(x));
    return __uint_as_float(r);
}

__device__ __forceinline__ void mma_tf32(float* c, const uint32_t* a, const uint32_t* b) {
    asm volatile(
        "mma.sync.aligned.m16n8k8.row.col.f32.tf32.tf32.f32 "
        "{%0,%1,%2,%3}, {%4,%5,%6,%7}, {%8,%9}, {%0,%1,%2,%3};"
        : "+f"(c[0]), "+f"(c[1]), "+f"(c[2]), "+f"(c[3])
        : "r"(a[0]), "r"(a[1]), "r"(a[2]), "r"(a[3]),
          "r"(b[0]), "r"(b[1]));
}

__device__ __forceinline__ void ldsm_x4(uint32_t& r0, uint32_t& r1,
                                        uint32_t& r2, uint32_t& r3, uint32_t addr) {
    asm volatile("ldmatrix.sync.aligned.m8n8.x4.shared.b16 {%0,%1,%2,%3}, [%4];"
                 : "=r"(r0), "=r"(r1), "=r"(r2), "=r"(r3) : "r"(addr));
}

// ---------------------------------------------------------------------------
// Pre-pass 1: tf32-round a buffer (float4 grid-stride).
// ---------------------------------------------------------------------------
__global__ void cvt_tf32_kernel(const float* __restrict__ src,
                                float* __restrict__ dst, int n4) {
    int i = blockIdx.x * blockDim.x + threadIdx.x;
    int stride = gridDim.x * blockDim.x;
    for (; i < n4; i += stride) {
        float4 v = *(const float4*)(src + (size_t)i * 4);
        v.x = f2tf32(v.x); v.y = f2tf32(v.y); v.z = f2tf32(v.z); v.w = f2tf32(v.w);
        *(float4*)(dst + (size_t)i * 4) = v;
    }
}

// ---------------------------------------------------------------------------
// Pre-pass 2: transpose + tf32-round. src [K][N] -> dst [N][K].
// ---------------------------------------------------------------------------
__global__ void transpose_tf32_kernel(const float* __restrict__ src,
                                      float* __restrict__ dst, int K, int N) {
    __shared__ float t[32][33];
    const int nb = blockIdx.x * 32;
    const int kb = blockIdx.y * 32;
    const int tx = threadIdx.x, ty = threadIdx.y;
#pragma unroll
    for (int i = 0; i < 32; i += 8)
        t[ty + i][tx] = f2tf32(src[(size_t)(kb + ty + i) * N + nb + tx]);
    __syncthreads();
#pragma unroll
    for (int i = 0; i < 32; i += 8)
        dst[(size_t)(nb + ty + i) * K + kb + tx] = t[tx][ty + i];
}

// ---------------------------------------------------------------------------
// Tensor-core tf32 GEMM (transposed-operand form), 3-stage cp.async pipeline,
// ONE __syncthreads per k-tile, ldmatrix fragment loads.
// C[M][N] = X[M][K] @ W[K][N] + bias; WT = W^T [N][K] pre-transposed.
// ---------------------------------------------------------------------------
#define BMT 128
#define BNT 128
#define BKT 32
#define XW_STR 36
#define TILE_SZ (128 * XW_STR)              // floats per (X or W) stage
#define G_STAGES 3
#define G_SMEM_FLOATS (2 * G_STAGES * TILE_SZ)
#define G_SMEM_BYTES  (G_SMEM_FLOATS * 4)   // 110592

__global__ __launch_bounds__(256, 2)
void gemm_tf32_bias_t(const float* __restrict__ X,   // [M][K] tf32-rounded
                      const float* __restrict__ WT,  // [N][K] tf32-rounded
                      const float* __restrict__ bias,
                      float* __restrict__ C,
                      int M, int N, int K) {
    extern __shared__ float sg[];
    float* XsBase = sg;                         // [3][128][36]
    float* WsBase = sg + G_STAGES * TILE_SZ;    // [3][128][36]

    const int tid  = threadIdx.x;
    const int warp = tid >> 5;
    const int lane = tid & 31;
    const int g    = lane >> 2;
    const int tig  = lane & 3;
    const int wtn  = warp >> 1;      // 0..3 : n-offset 32
    const int wtm  = warp & 1;       // 0..1 : m-offset 64
    const int m0   = blockIdx.y * BMT;
    const int n0   = blockIdx.x * BNT;

    const uint32_t smemX = (uint32_t)__cvta_generic_to_shared(XsBase);
    const uint32_t smemW = (uint32_t)__cvta_generic_to_shared(WsBase);

    const int lrA = (lane & 7) + ((lane >> 3) & 1) * 8;
    const int lcA = (lane >> 4) * 4;
    const int lrB = (lane & 7) + (lane >> 4) * 8;
    const int lcB = ((lane >> 3) & 1) * 4;

    const uint32_t aBase = smemW + (uint32_t)(((wtn * 32 + lrA) * XW_STR + lcA) << 2);
    const uint32_t bBase = smemX + (uint32_t)(((wtm * 64 + lrB) * XW_STR + lcB) << 2);

    float acc[2][8][4];
#pragma unroll
    for (int i = 0; i < 2; i++)
#pragma unroll
        for (int j = 0; j < 8; j++)
#pragma unroll
            for (int q = 0; q < 4; q++) acc[i][j][q] = 0.f;

    const int T = K / BKT;

    auto stage = [&](int kt, int st) {
#pragma unroll
        for (int i = 0; i < 4; i++) {
            int pos = tid + i * 256;
            int r   = pos >> 3;
            int cv  = (pos & 7) * 4;
            uint32_t dst = smemX + (uint32_t)((st * TILE_SZ + r * XW_STR + cv) << 2);
            const float* src = X + (size_t)(m0 + r) * K + kt + cv;
            int sz = (m0 + r < M) ? 16 : 0;
            asm volatile("cp.async.cg.shared.global [%0], [%1], 16, %2;\n"
                         :: "r"(dst), "l"(src), "r"(sz));
        }
#pragma unroll
        for (int i = 0; i < 4; i++) {
            int pos = tid + i * 256;
            int r   = pos >> 3;
            int cv  = (pos & 7) * 4;
            uint32_t dst = smemW + (uint32_t)((st * TILE_SZ + r * XW_STR + cv) << 2);
            const float* src = WT + (size_t)(n0 + r) * K + kt + cv;
            asm volatile("cp.async.cg.shared.global [%0], [%1], 16, 16;\n"
                         :: "r"(dst), "l"(src));
        }
        asm volatile("cp.async.commit_group;\n");
    };

    stage(0, 0);
    if (T > 1) stage(BKT, 1);

    for (int kt = 0; kt < T; kt++) {
        const int st = kt % 3;
        if (kt + 1 < T) {
            asm volatile("cp.async.wait_group 1;\n");
        } else {
            asm volatile("cp.async.wait_group 0;\n");
        }
        __syncthreads();
        // Buffer (kt+2)%3 was consumed at iteration kt-1; the sync above
        // guarantees every warp finished that compute. Safe to refill now.
        if (kt + 2 < T) stage((kt + 2) * BKT, (kt + 2) % 3);

        const uint32_t stOff = (uint32_t)(st * TILE_SZ * 4);

#pragma unroll
        for (int ks = 0; ks < 4; ks++) {
            const uint32_t kOff = (uint32_t)(ks * 8 * 4);
            uint32_t a[2][4];
#pragma unroll
            for (int i = 0; i < 2; i++)
                ldsm_x4(a[i][0], a[i][1], a[i][2], a[i][3],
                        aBase + stOff + (uint32_t)(i * 16 * XW_STR * 4) + kOff);
            uint32_t b[8][2];
#pragma unroll
            for (int j2 = 0; j2 < 4; j2++)
                ldsm_x4(b[2 * j2][0], b[2 * j2][1], b[2 * j2 + 1][0], b[2 * j2 + 1][1],
                        bBase + stOff + (uint32_t)(j2 * 16 * XW_STR * 4) + kOff);
#pragma unroll
            for (int i = 0; i < 2; i++)
#pragma unroll
                for (int j = 0; j < 8; j++)
                    mma_tf32(acc[i][j], a[i], b[j]);
        }
    }

#pragma unroll
    for (int i = 0; i < 2; i++) {
        const int na = n0 + wtn * 32 + i * 16 + g;
        const int nb = na + 8;
        const float bva = bias[na];
        const float bvb = bias[nb];
#pragma unroll
        for (int j = 0; j < 8; j++) {
            const int ma = m0 + wtm * 64 + j * 8 + 2 * tig;
            if (ma < M) {
                C[(size_t)ma * N + na] = acc[i][j][0] + bva;
                C[(size_t)ma * N + nb] = acc[i][j][2] + bvb;
            }
            if (ma + 1 < M) {
                C[(size_t)(ma + 1) * N + na] = acc[i][j][1] + bva;
                C[(size_t)(ma + 1) * N + nb] = acc[i][j][3] + bvb;
            }
        }
    }
}

// ---------------------------------------------------------------------------
// Kernel L: logits + bias + softmax -> probs. grid = 2400 (bh); loops the
// 4 q-blocks so K and rel tables are staged ONCE per (b,h).
// ---------------------------------------------------------------------------
#define KS_STR 68
#define T_STR  36

#define L_KS    0
#define L_QT    (L_KS  + 200 * KS_STR)
#define L_RPHT  (L_QT  + 64 * KS_STR)
#define L_RPWT  (L_RPHT + 64 * T_STR)
#define L_TH    (L_RPWT + 64 * T_STR)
#define L_TW    (L_TH  + 64 * T_STR)
#define L_REDA  (L_TW  + 64 * T_STR)
#define L_REDB  (L_REDA + 128)
#define L_QHW   (L_REDB + 128)
#define L_SMEM_FLOATS (L_QHW + 128)
#define L_SMEM_BYTES  (L_SMEM_FLOATS * 4)

__global__ __launch_bounds__(256, 2)
void attn_logits_kernel(const float* __restrict__ qkv,
                        const float* __restrict__ rph,
                        const float* __restrict__ rpw,
                        float* __restrict__ at_g) {
    extern __shared__ float sm[];
    float* Ks   = sm + L_KS;
    float* Qt   = sm + L_QT;
    float* rphT = sm + L_RPHT;
    float* rpwT = sm + L_RPWT;
    float* Th   = sm + L_TH;
    float* Tw   = sm + L_TW;
    float* redA = sm + L_REDA;
    float* redB = sm + L_REDB;
    int*   qhw  = (int*)(sm + L_QHW);

    const int bh   = blockIdx.x;
    const int b    = bh / NH;
    const int h    = bh % NH;
    const int tid  = threadIdx.x;
    const int warp = tid >> 5;
    const int lane = tid & 31;
    const int g    = lane >> 2;
    const int tig  = lane & 3;
    const int wm   = warp >> 1;
    const int wn   = warp & 1;
    const float scale = 0.125f;

    const float* qkv_b = qkv + (size_t)b * HW * QKV_N;

    // --- once per (b,h): rel tables + K tile ---
    for (int idx = tid; idx < 64 * T_STR; idx += 256) {
        int d = idx / T_STR;
        int j = idx % T_STR;
        rphT[d * T_STR + j] = (j < 2 * S_DIM - 1) ? f2tf32(rph[j * HD + d]) : 0.f;
        rpwT[d * T_STR + j] = (j < 2 * S_DIM - 1) ? f2tf32(rpw[j * HD + d]) : 0.f;
    }
    for (int slot = tid; slot < 200 * 16; slot += 256) {
        int s  = slot >> 4;
        int d4 = (slot & 15) << 2;
        float4 v = make_float4(0.f, 0.f, 0.f, 0.f);
        if (s < HW) {
            v = *(const float4*)(qkv_b + (size_t)s * QKV_N + C_DIM + h * HD + d4);
            v.x = f2tf32(v.x); v.y = f2tf32(v.y); v.z = f2tf32(v.z); v.w = f2tf32(v.w);
        }
        *(float4*)&Ks[s * KS_STR + d4] = v;
    }

    for (int qb = 0; qb < 4; qb++) {
        const int qbase = qb * 64;
        __syncthreads();   // protect Qt/Th/Tw/red/qhw reuse (and Ks/rel on first iter)

        // Stage Q block (tf32)
        for (int slot = tid; slot < 64 * 16; slot += 256) {
            int ql = slot >> 4;
            int d4 = (slot & 15) << 2;
            int s  = qbase + ql;
            float4 v = make_float4(0.f, 0.f, 0.f, 0.f);
            if (s < HW) {
                v = *(const float4*)(qkv_b + (size_t)s * QKV_N + h * HD + d4);
                v.x = f2tf32(v.x); v.y = f2tf32(v.y); v.z = f2tf32(v.z); v.w = f2tf32(v.w);
            }
            *(float4*)&Qt[ql * KS_STR + d4] = v;
        }
        if (tid < 64) {
            int s = qbase + tid;
            qhw[tid]      = s / S_DIM;
            qhw[64 + tid] = s % S_DIM;
        }
        __syncthreads();

        const int rB = wm * 16;
        uint32_t af[8][4];
#pragma unroll
        for (int kc = 0; kc < 8; kc++) {
            const int kb = kc * 8;
            af[kc][0] = __float_as_uint(Qt[(rB + g    ) * KS_STR + kb + tig    ]);
            af[kc][1] = __float_as_uint(Qt[(rB + g + 8) * KS_STR + kb + tig    ]);
            af[kc][2] = __float_as_uint(Qt[(rB + g    ) * KS_STR + kb + tig + 4]);
            af[kc][3] = __float_as_uint(Qt[(rB + g + 8) * KS_STR + kb + tig + 4]);
        }

        // T-mma: wn=0 -> Th ; wn=1 -> Tw
        {
            const float* Bt = wn ? rpwT : rphT;
            float*       Dt = wn ? Tw   : Th;
#pragma unroll
            for (int nt = 0; nt < 4; nt++) {
                float acc[4] = {0.f, 0.f, 0.f, 0.f};
                const int col = nt * 8 + g;
#pragma unroll
                for (int kc = 0; kc < 8; kc++) {
                    const int kb = kc * 8;
                    uint32_t bf[2];
                    bf[0] = __float_as_uint(Bt[(kb + tig    ) * T_STR + col]);
                    bf[1] = __float_as_uint(Bt[(kb + tig + 4) * T_STR + col]);
                    mma_tf32(acc, af[kc], bf);
                }
                const int c0 = nt * 8 + 2 * tig;
                Dt[(rB + g    ) * T_STR + c0    ] = acc[0];
                Dt[(rB + g    ) * T_STR + c0 + 1] = acc[1];
                Dt[(rB + g + 8) * T_STR + c0    ] = acc[2];
                Dt[(rB + g + 8) * T_STR + c0 + 1] = acc[3];
            }
        }
        __syncthreads();

        const int r0 = rB + g;
        const int r1 = r0 + 8;
        const int qh0 = qhw[r0],      qw0 = qhw[64 + r0];
        const int qh1 = qhw[r1],      qw1 = qhw[64 + r1];
        float lg[13][4];
#pragma unroll
        for (int it = 0; it < 13; it++) {
            const int nt  = wn * 13 + it;
            float acc[4] = {0.f, 0.f, 0.f, 0.f};
            const int col = nt * 8 + g;
#pragma unroll
            for (int kc = 0; kc < 8; kc++) {
                const int kb = kc * 8;
                uint32_t bf[2];
                bf[0] = __float_as_uint(Ks[col * KS_STR + kb + tig    ]);
                bf[1] = __float_as_uint(Ks[col * KS_STR + kb + tig + 4]);
                mma_tf32(acc, af[kc], bf);
            }
            const int c0 = nt * 8 + 2 * tig;
            const int c1 = c0 + 1;
            if (c0 < HW) {
                int kh = c0 / S_DIM, kw = c0 % S_DIM;
                lg[it][0] = acc[0] * scale + Th[r0 * T_STR + qh0 - kh + 13] + Tw[r0 * T_STR + qw0 - kw + 13];
                lg[it][2] = acc[2] * scale + Th[r1 * T_STR + qh1 - kh + 13] + Tw[r1 * T_STR + qw1 - kw + 13];
            } else { lg[it][0] = -1e30f; lg[it][2] = -1e30f; }
            if (c1 < HW) {
                int kh = c1 / S_DIM, kw = c1 % S_DIM;
                lg[it][1] = acc[1] * scale + Th[r0 * T_STR + qh0 - kh + 13] + Tw[r0 * T_STR + qw0 - kw + 13];
                lg[it][3] = acc[3] * scale + Th[r1 * T_STR + qh1 - kh + 13] + Tw[r1 * T_STR + qw1 - kw + 13];
            } else { lg[it][1] = -1e30f; lg[it][3] = -1e30f; }
        }

        float m0 = -1e30f, m1 = -1e30f;
#pragma unroll
        for (int it = 0; it < 13; it++) {
            m0 = fmaxf(m0, fmaxf(lg[it][0], lg[it][1]));
            m1 = fmaxf(m1, fmaxf(lg[it][2], lg[it][3]));
        }
        m0 = fmaxf(m0, __shfl_xor_sync(0xffffffffu, m0, 1));
        m0 = fmaxf(m0, __shfl_xor_sync(0xffffffffu, m0, 2));
        m1 = fmaxf(m1, __shfl_xor_sync(0xffffffffu, m1, 1));
        m1 = fmaxf(m1, __shfl_xor_sync(0xffffffffu, m1, 2));
        if (tig == 0) { redA[wn * 64 + r0] = m0; redA[wn * 64 + r1] = m1; }
        __syncthreads();
        const float M0 = fmaxf(redA[r0], redA[64 + r0]);
        const float M1 = fmaxf(redA[r1], redA[64 + r1]);

        float s0 = 0.f, s1 = 0.f;
#pragma unroll
        for (int it = 0; it < 13; it++) {
            float e0 = __expf(lg[it][0] - M0); lg[it][0] = e0; s0 += e0;
            float e1 = __expf(lg[it][1] - M0); lg[it][1] = e1; s0 += e1;
            float e2 = __expf(lg[it][2] - M1); lg[it][2] = e2; s1 += e2;
            float e3 = __expf(lg[it][3] - M1); lg[it][3] = e3; s1 += e3;
        }
        s0 += __shfl_xor_sync(0xffffffffu, s0, 1);
        s0 += __shfl_xor_sync(0xffffffffu, s0, 2);
        s1 += __shfl_xor_sync(0xffffffffu, s1, 1);
        s1 += __shfl_xor_sync(0xffffffffu, s1, 2);
        if (tig == 0) { redB[wn * 64 + r0] = s0; redB[wn * 64 + r1] = s1; }
        __syncthreads();
        const float inv0 = 1.0f / (redB[r0] + redB[64 + r0]);
        const float inv1 = 1.0f / (redB[r1] + redB[64 + r1]);

        const int row0 = qbase + r0;
        const int row1 = qbase + r1;
        float* atr0 = at_g + ((size_t)bh * HW + row0) * 200;
        float* atr1 = at_g + ((size_t)bh * HW + row1) * 200;
#pragma unroll
        for (int it = 0; it < 13; it++) {
            const int nt = wn * 13 + it;
            const int c0 = nt * 8 + 2 * tig;
            if (c0 < HW) {
                if (row0 < HW) {
                    float2 p = make_float2(f2tf32(lg[it][0] * inv0), f2tf32(lg[it][1] * inv0));
                    *(float2*)(atr0 + c0) = p;
                }
                if (row1 < HW) {
                    float2 p = make_float2(f2tf32(lg[it][2] * inv1), f2tf32(lg[it][3] * inv1));
                    *(float2*)(atr1 + c0) = p;
                }
            }
        }
    }
}

// ---------------------------------------------------------------------------
// Kernel V: out = probs @ V. ctx stored tf32-rounded. (unchanged)
// ---------------------------------------------------------------------------
#define V_STR  72
#define AT_STR 204
#define V_SMEM_FLOATS (200 * V_STR + 64 * AT_STR)
#define V_SMEM_BYTES  (V_SMEM_FLOATS * 4)

__global__ __launch_bounds__(256, 2)
void attn_av_kernel(const float* __restrict__ qkv,
                    const float* __restrict__ at_g,
                    float* __restrict__ ctx) {
    extern __shared__ float sm[];
    float* Vs  = sm;
    float* atS = sm + 200 * V_STR;

    const int bh   = blockIdx.x;
    const int b    = bh / NH;
    const int h    = bh % NH;
    const int tid  = threadIdx.x;
    const int warp = tid >> 5;
    const int lane = tid & 31;
    const int g    = lane >> 2;
    const int tig  = lane & 3;
    const int wm   = warp >> 1;
    const int wn   = warp & 1;

    const float* qkv_b = qkv + (size_t)b * HW * QKV_N;
    const float* at_b  = at_g + (size_t)bh * HW * 200;

    for (int slot = tid; slot < 200 * 16; slot += 256) {
        int s  = slot >> 4;
        int d4 = (slot & 15) << 2;
        float4 v = make_float4(0.f, 0.f, 0.f, 0.f);
        if (s < HW) {
            v = *(const float4*)(qkv_b + (size_t)s * QKV_N + 2 * C_DIM + h * HD + d4);
            v.x = f2tf32(v.x); v.y = f2tf32(v.y); v.z = f2tf32(v.z); v.w = f2tf32(v.w);
        }
        *(float4*)&Vs[s * V_STR + d4] = v;
    }

    for (int qb = 0; qb < 4; qb++) {
        const int qbase = qb * 64;
        __syncthreads();

        for (int slot = tid; slot < 64 * 50; slot += 256) {
            int rr = slot / 50;
            int c4 = slot % 50;
            int s  = qbase + rr;
            float4 v = make_float4(0.f, 0.f, 0.f, 0.f);
            if (s < HW && c4 < 49)
                v = *(const float4*)(at_b + (size_t)s * 200 + c4 * 4);
            *(float4*)&atS[rr * AT_STR + c4 * 4] = v;
        }
        __syncthreads();

        const int rB = wm * 16;
        float acc[4][4];
#pragma unroll
        for (int nt = 0; nt < 4; nt++)
#pragma unroll
            for (int i = 0; i < 4; i++) acc[nt][i] = 0.f;

        for (int kc = 0; kc < 25; kc++) {
            const int kb = kc * 8;
            uint32_t a[4];
            a[0] = __float_as_uint(atS[(rB + g    ) * AT_STR + kb + tig    ]);
            a[1] = __float_as_uint(atS[(rB + g + 8) * AT_STR + kb + tig    ]);
            a[2] = __float_as_uint(atS[(rB + g    ) * AT_STR + kb + tig + 4]);
            a[3] = __float_as_uint(atS[(rB + g + 8) * AT_STR + kb + tig + 4]);
#pragma unroll
            for (int nt = 0; nt < 4; nt++) {
                const int col = wn * 32 + nt * 8 + g;
                uint32_t bf[2];
                bf[0] = __float_as_uint(Vs[(kb + tig    ) * V_STR + col]);
                bf[1] = __float_as_uint(Vs[(kb + tig + 4) * V_STR + col]);
                mma_tf32(acc[nt], a, bf);
            }
        }

        const int s0 = qbase + rB + g;
        const int s1 = s0 + 8;
#pragma unroll
        for (int nt = 0; nt < 4; nt++) {
            const int d = wn * 32 + nt * 8 + 2 * tig;
            if (s0 < HW) {
                float2 r0 = make_float2(f2tf32(acc[nt][0]), f2tf32(acc[nt][1]));
                *(float2*)(ctx + (size_t)(b * HW + s0) * C_DIM + h * HD + d) = r0;
            }
            if (s1 < HW) {
                float2 r1 = make_float2(f2tf32(acc[nt][2]), f2tf32(acc[nt][3]));
                *(float2*)(ctx + (size_t)(b * HW + s1) * C_DIM + h * HD + d) = r1;
            }
        }
    }
}

// ---------------------------------------------------------------------------
extern "C" void kernel_launch(void* const* d_in, const int* in_sizes, int n_in,
                              void* d_out, int out_size) {
    const float* x      = (const float*)d_in[0];
    const float* w_qkv  = (const float*)d_in[1];
    const float* b_qkv  = (const float*)d_in[2];
    const float* w_proj = (const float*)d_in[3];
    const float* b_proj = (const float*)d_in[4];
    const float* rph    = (const float*)d_in[5];
    const float* rpw    = (const float*)d_in[6];
    float* out = (float*)d_out;

    float *qkv_ptr, *ctx_ptr, *at_ptr, *xc_ptr, *wqT_ptr, *wpT_ptr;
    cudaGetSymbolAddress((void**)&qkv_ptr, g_qkv);
    cudaGetSymbolAddress((void**)&ctx_ptr, g_ctx);
    cudaGetSymbolAddress((void**)&at_ptr, g_at);
    cudaGetSymbolAddress((void**)&xc_ptr, g_xc);
    cudaGetSymbolAddress((void**)&wqT_ptr, g_wqkvT);
    cudaGetSymbolAddress((void**)&wpT_ptr, g_wprojT);

    static bool attr_set = false;
    if (!attr_set) {
        cudaFuncSetAttribute(gemm_tf32_bias_t,
                             cudaFuncAttributeMaxDynamicSharedMemorySize,
                             G_SMEM_BYTES);
        cudaFuncSetAttribute(attn_logits_kernel,
                             cudaFuncAttributeMaxDynamicSharedMemorySize,
                             L_SMEM_BYTES);
        cudaFuncSetAttribute(attn_av_kernel,
                             cudaFuncAttributeMaxDynamicSharedMemorySize,
                             V_SMEM_BYTES);
        attr_set = true;
    }

    // 0) Pre-pass: tf32-round x; transpose + tf32-round weights
    cvt_tf32_kernel<<<592, 256>>>(x, xc_ptr, M_TOK * C_DIM / 4);
    {
        dim3 blk(32, 8);
        dim3 gq(QKV_N / 32, C_DIM / 32);
        transpose_tf32_kernel<<<gq, blk>>>(w_qkv, wqT_ptr, C_DIM, QKV_N);
        dim3 gp(C_DIM / 32, C_DIM / 32);
        transpose_tf32_kernel<<<gp, blk>>>(w_proj, wpT_ptr, C_DIM, C_DIM);
    }

    // 1) QKV projection (3-stage pipeline, single-sync mainloop)
    {
        dim3 grid(QKV_N / BNT, (M_TOK + BMT - 1) / BMT);   // 18 x 307
        gemm_tf32_bias_t<<<grid, 256, G_SMEM_BYTES>>>(xc_ptr, wqT_ptr, b_qkv, qkv_ptr,
                                                      M_TOK, QKV_N, C_DIM);
    }

    // 2a) Logits + bias + softmax -> probs (K staged once per head)
    attn_logits_kernel<<<NHEADS_TOT, 256, L_SMEM_BYTES>>>(qkv_ptr, rph, rpw, at_ptr);

    // 2b) AV (ctx written tf32-rounded)
    attn_av_kernel<<<NHEADS_TOT, 256, V_SMEM_BYTES>>>(qkv_ptr, at_ptr, ctx_ptr);

    // 3) Output projection
    {
        dim3 grid(C_DIM / BNT, (M_TOK + BMT - 1) / BMT);   // 6 x 307
        gemm_tf32_bias_t<<<grid, 256, G_SMEM_BYTES>>>(ctx_ptr, wpT_ptr, b_proj, out,
                                                      M_TOK, C_DIM, C_DIM);
    }
}